// round 8
// baseline (speedup 1.0000x reference)
#include <cuda_runtime.h>

namespace {

constexpr int Hh = 8, Ll = 2048, Dd = 512;
constexpr float PIf = 3.14159265358979323846f;
using u64 = unsigned long long;

// ---- packed f32x2 complex ops (re in lane0, im in lane1) -------------------
__device__ __forceinline__ u64 pk2(float x, float y) {
  u64 r; asm("mov.b64 %0, {%1, %2};" : "=l"(r) : "f"(x), "f"(y)); return r;
}
__device__ __forceinline__ void unpk(u64 v, float& x, float& y) {
  asm("mov.b64 {%0, %1}, %2;" : "=f"(x), "=f"(y) : "l"(v));
}
__device__ __forceinline__ u64 padd(u64 a, u64 b) {
  u64 r; asm("add.rn.f32x2 %0, %1, %2;" : "=l"(r) : "l"(a), "l"(b)); return r;
}
__device__ __forceinline__ u64 pmul(u64 a, u64 b) {
  u64 r; asm("mul.rn.f32x2 %0, %1, %2;" : "=l"(r) : "l"(a), "l"(b)); return r;
}
__device__ __forceinline__ u64 pfma(u64 a, u64 b, u64 c) {
  u64 r; asm("fma.rn.f32x2 %0, %1, %2, %3;" : "=l"(r) : "l"(a), "l"(b), "l"(c)); return r;
}
__device__ __forceinline__ u64 pswap(u64 v) { float x, y; unpk(v, x, y); return pk2(y, x); }
template<int S>
__device__ __forceinline__ u64 prot(u64 v) {   // * -i (S<0) or * +i (S>0)
  float x, y; unpk(v, x, y);
  return (S < 0) ? pk2(y, -x) : pk2(-y, x);
}
// scalar-twiddle complex multiply on a packed value
__device__ __forceinline__ u64 cmulsc(u64 v, float c, float s) {
  float x, y; unpk(v, x, y);
  return pk2(x * c - y * s, x * s + y * c);
}

// 8-point DFT on packed values, natural order. S=-1 forward, +1 inverse.
template<int S>
__device__ __forceinline__ void dft8p(u64 v[8]) {
  const float r = 0.70710678118654752440f;
  const u64 NEG1 = pk2(-1.f, -1.f);
  const u64 PM   = pk2( 1.f, -1.f);
  const u64 MP   = pk2(-1.f,  1.f);
  const u64 RR   = pk2(  r,    r);
  const u64 NR   = pk2( -r,   -r);
  auto psub = [&](u64 a, u64 b) { return pfma(b, NEG1, a); };

  u64 a0 = padd(v[0], v[4]), a1 = padd(v[1], v[5]);
  u64 a2 = padd(v[2], v[6]), a3 = padd(v[3], v[7]);
  u64 b0 = psub(v[0], v[4]), b1 = psub(v[1], v[5]);
  u64 b2 = psub(v[2], v[6]), b3 = psub(v[3], v[7]);

  b1 = pmul(pfma(pswap(b1), (S < 0) ? PM : MP, b1), RR);   // *W8^S
  b3 = pmul(pfma(pswap(b3), (S < 0) ? MP : PM, b3), NR);   // *W8^{3S}
  b2 = prot<S>(b2);

  {
    u64 e0 = padd(a0, a2), e1 = padd(a1, a3);
    u64 o0 = psub(a0, a2), t1 = psub(a1, a3);
    u64 o1 = prot<S>(t1);
    v[0] = padd(e0, e1); v[4] = psub(e0, e1);
    v[2] = padd(o0, o1); v[6] = psub(o0, o1);
  }
  {
    u64 e0 = padd(b0, b2), e1 = padd(b1, b3);
    u64 o0 = psub(b0, b2), t1 = psub(b1, b3);
    u64 o1 = prot<S>(t1);
    v[1] = padd(e0, e1); v[5] = psub(e0, e1);
    v[3] = padd(o0, o1); v[7] = psub(o0, o1);
  }
}

// Geometric twiddle stage: v[k] *= e^{i k th}, k=1..7.
// Odd harmonics from MUFU (__sincosf), evens by double-angle squaring.
__device__ __forceinline__ void twiddle8(u64 v[8], float th) {
  float c1, s1; __sincosf(th, &s1, &c1);
  v[1] = cmulsc(v[1], c1, s1);
  float c2 = c1 * c1 - s1 * s1, s2 = 2.f * c1 * s1;
  v[2] = cmulsc(v[2], c2, s2);
  float c3, s3; __sincosf(3.f * th, &s3, &c3);
  v[3] = cmulsc(v[3], c3, s3);
  float c4 = c2 * c2 - s2 * s2, s4 = 2.f * c2 * s2;
  v[4] = cmulsc(v[4], c4, s4);
  float c5, s5; __sincosf(5.f * th, &s5, &c5);
  v[5] = cmulsc(v[5], c5, s5);
  float c6 = c3 * c3 - s3 * s3, s6 = 2.f * c3 * s3;
  v[6] = cmulsc(v[6], c6, s6);
  float c7, s7; __sincosf(7.f * th, &s7, &c7);
  v[7] = cmulsc(v[7], c7, s7);
}

// Half-warp phase-conflict-free swizzle for 8B values, logical 64a + 8b + c.
// phys [8:4] = (a2,a1,b2,b1,b0); [3:0] = (a0^b0, c2^b2, c1^b1, c0^b0).
// Invertible on each access pattern's half-warp free-bit subspace =>
// 2 wavefronts per 8B instruction (the floor) on every exchange and the gate.
__device__ __forceinline__ int swz(int a, int b, int c) {
  return ((a >> 1) << 7) | ((b >> 1) << 5) | ((b & 1) << 4)
       | (((a ^ b) & 1) << 3) | ((b ^ c) & 7);
}

// Per-row barrier: the two warps of pair-row s sync on named barrier 1+s.
__device__ __forceinline__ void row_sync(int s) {
  asm volatile("bar.sync %0, 64;" :: "r"(1 + s) : "memory");
}

// One block = one (h,l): 4 independent pair-rows (s pairs batches s and s+4),
// 64 threads per pair-row. Radix-8 FFT512 (DIF fwd, digit-rev spectrum,
// DIT inv). Gate staged once per block; rows sync on per-row named barriers.
__global__ void __launch_bounds__(256, 5)
sgn_fft_kernel(const float* __restrict__ x, const float* __restrict__ wgt,
               float* __restrict__ out)
{
  __shared__ u64 sm[4][512];
  __shared__ float2 Vsm[512];

  const int tid = threadIdx.x;
  const int s   = tid >> 6;
  const int t   = tid & 63;
  const int hl  = blockIdx.x;          // hl = h*2048 + l

  const float2* __restrict__ wrow =
      reinterpret_cast<const float2*>(wgt) + (size_t)hl * Dd;

  // ---- gate staging with Hermitian pairing:
  // V_k = (W_k + conj(W_{-k})) / 1024  and  V_{512-k} = conj(V_k).
  // Thread tid handles k = tid (0..255) and its mirror 512-tid; thread 0
  // additionally handles the self-paired k = 256.
  {
    const int j = tid;                     // 0..255
    const int m = (512 - j) & 511;         // 0 or 257..511
    float2 wk = __ldg(&wrow[j]);
    float2 wm = __ldg(&wrow[m]);
    float vx = (wk.x + wm.x) * (1.f / 1024.f);
    float vy = (wk.y - wm.y) * (1.f / 1024.f);
    Vsm[swz(j >> 6, (j >> 3) & 7, j & 7)] = make_float2(vx, vy);
    Vsm[swz(m >> 6, (m >> 3) & 7, m & 7)] = make_float2(vx, -vy);
    if (tid == 0) {
      float2 w2 = __ldg(&wrow[256]);
      Vsm[swz(256 >> 6, (256 >> 3) & 7, 0)] =
          make_float2(2.f * w2.x * (1.f / 1024.f), 0.f);
    }
  }

  // 32-bit element offsets (B*H*L*D = 2^26 < 2^31)
  const unsigned rowStride = (unsigned)(Hh * Ll) * (unsigned)Dd; // per-batch
  const unsigned base = (unsigned)hl * (unsigned)Dd;
  const unsigned off1 = (unsigned)s * rowStride + base;
  const unsigned off2 = off1 + 4u * rowStride;
  const float* __restrict__ x1 = x + off1;
  const float* __restrict__ x2 = x + off2;

  u64 v[8];
  // z = x1 + i*x2, n = 64*n2 + t
#pragma unroll
  for (int n2 = 0; n2 < 8; ++n2)
    v[n2] = pk2(__ldg(&x1[(n2 << 6) + t]), __ldg(&x2[(n2 << 6) + t]));

  // ---- forward stage 1: DFT over n2 -> k0, twiddle e^{-2pi i t k0/512}
  dft8p<-1>(v);
  twiddle8(v, -2.f * PIf * (float)t * (1.f / 512.f));
  {
    const int n1 = t >> 3, n0 = t & 7;
#pragma unroll
    for (int k = 0; k < 8; ++k) sm[s][swz(k, n1, n0)] = v[k];
  }
  // full-block barrier: orders sm[s] AND the shared Vsm staging
  __syncthreads();

  // ---- forward stage 2: thread (k0, n0), DFT over n1 -> k1, tw e^{-2pi i n0 k1/64}
  const int k0 = t >> 3;
  const int n0 = t & 7;
#pragma unroll
  for (int j = 0; j < 8; ++j) v[j] = sm[s][swz(k0, j, n0)];
  dft8p<-1>(v);
  twiddle8(v, -2.f * PIf * (float)n0 * (1.f / 64.f));
#pragma unroll
  for (int k = 0; k < 8; ++k) sm[s][swz(k0, k, n0)] = v[k];
  row_sync(s);

  // ---- forward stage 3 (registers): thread (k0, k1), DFT over n0 -> k2
  const int k1 = t & 7;
#pragma unroll
  for (int c = 0; c < 8; ++c) v[c] = sm[s][swz(k0, k1, c)];
  dft8p<-1>(v);
  // v[k2] = Z[k] at k = k0 + 8*k1 + 64*k2

  // ---- spectral gate (conflict-free smem)
#pragma unroll
  for (int k2 = 0; k2 < 8; ++k2) {
    float2 Vv = Vsm[swz(k2, k1, k0)];
    v[k2] = cmulsc(v[k2], Vv.x, Vv.y);
  }

  // ---- inverse stage 3': IDFT over k2 -> n0', twiddle e^{+2pi i n0' k1/64}
  dft8p<1>(v);
  twiddle8(v, 2.f * PIf * (float)k1 * (1.f / 64.f));
#pragma unroll
  for (int c = 0; c < 8; ++c) sm[s][swz(k0, k1, c)] = v[c];
  row_sync(s);

  // ---- inverse stage 2': thread (k0, n0), IDFT over k1 -> n1,
  //      twiddle e^{+2pi i (8*n1+n0)*k0/512} via direct MUFU sincos
#pragma unroll
  for (int j = 0; j < 8; ++j) v[j] = sm[s][swz(k0, j, n0)];
  dft8p<1>(v);
  {
    const float thb = 2.f * PIf * (1.f / 512.f) * (float)k0;
#pragma unroll
    for (int n1 = 0; n1 < 8; ++n1) {
      float sn, cs; __sincosf(thb * (float)((n1 << 3) + n0), &sn, &cs);
      v[n1] = cmulsc(v[n1], cs, sn);
    }
  }
#pragma unroll
  for (int n1 = 0; n1 < 8; ++n1) sm[s][swz(k0, n1, n0)] = v[n1];
  row_sync(s);

  // ---- inverse stage 1': thread t=(n1,n0), IDFT over k0 -> n2, store
#pragma unroll
  for (int a = 0; a < 8; ++a) v[a] = sm[s][swz(a, t >> 3, t & 7)];
  dft8p<1>(v);

  float* __restrict__ o1 = out + off1;
  float* __restrict__ o2 = out + off2;
#pragma unroll
  for (int n2 = 0; n2 < 8; ++n2) {
    float re, im; unpk(v[n2], re, im);
    o1[(n2 << 6) + t] = re;   // Re -> batch s
    o2[(n2 << 6) + t] = im;   // Im -> batch s+4
  }
}

} // namespace

extern "C" void kernel_launch(void* const* d_in, const int* in_sizes, int n_in,
                              void* d_out, int out_size) {
  const float* x   = (const float*)d_in[0];
  // d_in[1] is the (unused) mask
  const float* wgt = (const float*)d_in[2];
  float* out       = (float*)d_out;
  sgn_fft_kernel<<<Hh * Ll, 256>>>(x, wgt, out);
}

// round 9
// speedup vs baseline: 1.0471x; 1.0471x over previous
#include <cuda_runtime.h>

namespace {

constexpr int Hh = 8, Ll = 2048, Dd = 512;
constexpr float PIf = 3.14159265358979323846f;
using u64 = unsigned long long;

// ---- packed f32x2 complex ops (re in lane0, im in lane1) -------------------
__device__ __forceinline__ u64 pk2(float x, float y) {
  u64 r; asm("mov.b64 %0, {%1, %2};" : "=l"(r) : "f"(x), "f"(y)); return r;
}
__device__ __forceinline__ void unpk(u64 v, float& x, float& y) {
  asm("mov.b64 {%0, %1}, %2;" : "=f"(x), "=f"(y) : "l"(v));
}
__device__ __forceinline__ u64 padd(u64 a, u64 b) {
  u64 r; asm("add.rn.f32x2 %0, %1, %2;" : "=l"(r) : "l"(a), "l"(b)); return r;
}
__device__ __forceinline__ u64 pmul(u64 a, u64 b) {
  u64 r; asm("mul.rn.f32x2 %0, %1, %2;" : "=l"(r) : "l"(a), "l"(b)); return r;
}
__device__ __forceinline__ u64 pfma(u64 a, u64 b, u64 c) {
  u64 r; asm("fma.rn.f32x2 %0, %1, %2, %3;" : "=l"(r) : "l"(a), "l"(b), "l"(c)); return r;
}
__device__ __forceinline__ u64 pswap(u64 v) { float x, y; unpk(v, x, y); return pk2(y, x); }
template<int S>
__device__ __forceinline__ u64 prot(u64 v) {   // * -i (S<0) or * +i (S>0)
  float x, y; unpk(v, x, y);
  return (S < 0) ? pk2(y, -x) : pk2(-y, x);
}
// scalar-twiddle complex multiply on a packed value
__device__ __forceinline__ u64 cmulsc(u64 v, float c, float s) {
  float x, y; unpk(v, x, y);
  return pk2(x * c - y * s, x * s + y * c);
}

// 8-point DFT on packed values, natural order. S=-1 forward, +1 inverse.
template<int S>
__device__ __forceinline__ void dft8p(u64 v[8]) {
  const float r = 0.70710678118654752440f;
  const u64 NEG1 = pk2(-1.f, -1.f);
  const u64 PM   = pk2( 1.f, -1.f);
  const u64 MP   = pk2(-1.f,  1.f);
  const u64 RR   = pk2(  r,    r);
  const u64 NR   = pk2( -r,   -r);
  auto psub = [&](u64 a, u64 b) { return pfma(b, NEG1, a); };

  u64 a0 = padd(v[0], v[4]), a1 = padd(v[1], v[5]);
  u64 a2 = padd(v[2], v[6]), a3 = padd(v[3], v[7]);
  u64 b0 = psub(v[0], v[4]), b1 = psub(v[1], v[5]);
  u64 b2 = psub(v[2], v[6]), b3 = psub(v[3], v[7]);

  b1 = pmul(pfma(pswap(b1), (S < 0) ? PM : MP, b1), RR);   // *W8^S
  b3 = pmul(pfma(pswap(b3), (S < 0) ? MP : PM, b3), NR);   // *W8^{3S}
  b2 = prot<S>(b2);

  {
    u64 e0 = padd(a0, a2), e1 = padd(a1, a3);
    u64 o0 = psub(a0, a2), t1 = psub(a1, a3);
    u64 o1 = prot<S>(t1);
    v[0] = padd(e0, e1); v[4] = psub(e0, e1);
    v[2] = padd(o0, o1); v[6] = psub(o0, o1);
  }
  {
    u64 e0 = padd(b0, b2), e1 = padd(b1, b3);
    u64 o0 = psub(b0, b2), t1 = psub(b1, b3);
    u64 o1 = prot<S>(t1);
    v[1] = padd(e0, e1); v[5] = psub(e0, e1);
    v[3] = padd(o0, o1); v[7] = psub(o0, o1);
  }
}

// Geometric twiddle stage: v[k] *= e^{i k th}, k=1..7.
// Odd harmonics from MUFU (__sincosf), evens by double-angle squaring.
__device__ __forceinline__ void twiddle8(u64 v[8], float th) {
  float c1, s1; __sincosf(th, &s1, &c1);
  v[1] = cmulsc(v[1], c1, s1);
  float c2 = c1 * c1 - s1 * s1, s2 = 2.f * c1 * s1;
  v[2] = cmulsc(v[2], c2, s2);
  float c3, s3; __sincosf(3.f * th, &s3, &c3);
  v[3] = cmulsc(v[3], c3, s3);
  float c4 = c2 * c2 - s2 * s2, s4 = 2.f * c2 * s2;
  v[4] = cmulsc(v[4], c4, s4);
  float c5, s5; __sincosf(5.f * th, &s5, &c5);
  v[5] = cmulsc(v[5], c5, s5);
  float c6 = c3 * c3 - s3 * s3, s6 = 2.f * c3 * s3;
  v[6] = cmulsc(v[6], c6, s6);
  float c7, s7; __sincosf(7.f * th, &s7, &c7);
  v[7] = cmulsc(v[7], c7, s7);
}

// Half-warp phase-conflict-free swizzle for 8B values, logical 64a + 8b + c.
// phys [8:4] = (a2,a1,b2,b1,b0); [3:0] = (a0^b0, c2^b2, c1^b1, c0^b0).
// Invertible on each access pattern's half-warp free-bit subspace =>
// 2 wavefronts per 8B instruction (the floor) on every exchange and the gate.
__device__ __forceinline__ int swz(int a, int b, int c) {
  return ((a >> 1) << 7) | ((b >> 1) << 5) | ((b & 1) << 4)
       | (((a ^ b) & 1) << 3) | ((b ^ c) & 7);
}

// One block = HALF an (h,l) tile: 2 pair-rows, 128 threads, 10 blocks/SM.
// Small blocks decorrelate barrier waits across the SM (10 independent
// barrier domains) while restoring high occupancy (HW-barrier pool no
// longer binds; regs do: 51-reg target).
// Pair-row handles batches pb and pb+4 packed as z = x1 + i*x2.
__global__ void __launch_bounds__(128, 10)
sgn_fft_kernel(const float* __restrict__ x, const float* __restrict__ wgt,
               float* __restrict__ out)
{
  __shared__ u64 sm[2][512];
  __shared__ float2 Vsm[512];

  const int tid  = threadIdx.x;
  const int s    = tid >> 6;              // pair-row within block (0..1)
  const int t    = tid & 63;
  const int bid  = blockIdx.x;
  const int hl   = bid >> 1;              // hl = h*2048 + l
  const int pb   = ((bid & 1) << 1) | s;  // batch pair 0..3

  const float2* __restrict__ wrow =
      reinterpret_cast<const float2*>(wgt) + (size_t)hl * Dd;

  // ---- gate staging with Hermitian pairing:
  // V_k = (W_k + conj(W_{-k})) / 1024 and V_{512-k} = conj(V_k).
  // Threads handle k = tid, tid+128 and their mirrors; tid 0 adds k=256.
#pragma unroll
  for (int i = tid; i < 256; i += 128) {
    const int m = (512 - i) & 511;
    float2 wk = __ldg(&wrow[i]);
    float2 wm = __ldg(&wrow[m]);
    float vx = (wk.x + wm.x) * (1.f / 1024.f);
    float vy = (wk.y - wm.y) * (1.f / 1024.f);
    Vsm[swz(i >> 6, (i >> 3) & 7, i & 7)] = make_float2(vx, vy);
    Vsm[swz(m >> 6, (m >> 3) & 7, m & 7)] = make_float2(vx, -vy);
  }
  if (tid == 0) {
    float2 w2 = __ldg(&wrow[256]);
    Vsm[swz(4, 0, 0)] = make_float2(2.f * w2.x * (1.f / 1024.f), 0.f);
  }

  // 32-bit element offsets (B*H*L*D = 2^26 < 2^31)
  const unsigned rowStride = (unsigned)(Hh * Ll) * (unsigned)Dd; // per-batch
  const unsigned base = (unsigned)hl * (unsigned)Dd;
  const unsigned off1 = (unsigned)pb * rowStride + base;
  const unsigned off2 = off1 + 4u * rowStride;
  const float* __restrict__ x1 = x + off1;
  const float* __restrict__ x2 = x + off2;

  u64 v[8];
  // z = x1 + i*x2, n = 64*n2 + t
#pragma unroll
  for (int n2 = 0; n2 < 8; ++n2)
    v[n2] = pk2(__ldg(&x1[(n2 << 6) + t]), __ldg(&x2[(n2 << 6) + t]));

  // ---- forward stage 1: DFT over n2 -> k0, twiddle e^{-2pi i t k0/512}
  dft8p<-1>(v);
  twiddle8(v, -2.f * PIf * (float)t * (1.f / 512.f));
  {
    const int n1 = t >> 3, n0 = t & 7;
#pragma unroll
    for (int k = 0; k < 8; ++k) sm[s][swz(k, n1, n0)] = v[k];
  }
  // orders sm[s] AND the shared Vsm staging
  __syncthreads();

  // ---- forward stage 2: thread (k0, n0), DFT over n1 -> k1, tw e^{-2pi i n0 k1/64}
  const int k0 = t >> 3;
  const int n0 = t & 7;
#pragma unroll
  for (int j = 0; j < 8; ++j) v[j] = sm[s][swz(k0, j, n0)];
  dft8p<-1>(v);
  twiddle8(v, -2.f * PIf * (float)n0 * (1.f / 64.f));
#pragma unroll
  for (int k = 0; k < 8; ++k) sm[s][swz(k0, k, n0)] = v[k];
  __syncthreads();

  // ---- forward stage 3 (registers): thread (k0, k1), DFT over n0 -> k2
  const int k1 = t & 7;
#pragma unroll
  for (int c = 0; c < 8; ++c) v[c] = sm[s][swz(k0, k1, c)];
  dft8p<-1>(v);
  // v[k2] = Z[k] at k = k0 + 8*k1 + 64*k2

  // ---- spectral gate (conflict-free smem)
#pragma unroll
  for (int k2 = 0; k2 < 8; ++k2) {
    float2 Vv = Vsm[swz(k2, k1, k0)];
    v[k2] = cmulsc(v[k2], Vv.x, Vv.y);
  }

  // ---- inverse stage 3': IDFT over k2 -> n0', twiddle e^{+2pi i n0' k1/64}
  dft8p<1>(v);
  twiddle8(v, 2.f * PIf * (float)k1 * (1.f / 64.f));
#pragma unroll
  for (int c = 0; c < 8; ++c) sm[s][swz(k0, k1, c)] = v[c];
  __syncthreads();

  // ---- inverse stage 2': thread (k0, n0), IDFT over k1 -> n1,
  //      twiddle e^{+2pi i (8*n1+n0)*k0/512} via direct MUFU sincos
#pragma unroll
  for (int j = 0; j < 8; ++j) v[j] = sm[s][swz(k0, j, n0)];
  dft8p<1>(v);
  {
    const float thb = 2.f * PIf * (1.f / 512.f) * (float)k0;
#pragma unroll
    for (int n1 = 0; n1 < 8; ++n1) {
      float sn, cs; __sincosf(thb * (float)((n1 << 3) + n0), &sn, &cs);
      v[n1] = cmulsc(v[n1], cs, sn);
    }
  }
#pragma unroll
  for (int n1 = 0; n1 < 8; ++n1) sm[s][swz(k0, n1, n0)] = v[n1];
  __syncthreads();

  // ---- inverse stage 1': thread t=(n1,n0), IDFT over k0 -> n2, store
#pragma unroll
  for (int a = 0; a < 8; ++a) v[a] = sm[s][swz(a, t >> 3, t & 7)];
  dft8p<1>(v);

  float* __restrict__ o1 = out + off1;
  float* __restrict__ o2 = out + off2;
#pragma unroll
  for (int n2 = 0; n2 < 8; ++n2) {
    float re, im; unpk(v[n2], re, im);
    o1[(n2 << 6) + t] = re;   // Re -> batch pb
    o2[(n2 << 6) + t] = im;   // Im -> batch pb+4
  }
}

} // namespace

extern "C" void kernel_launch(void* const* d_in, const int* in_sizes, int n_in,
                              void* d_out, int out_size) {
  const float* x   = (const float*)d_in[0];
  // d_in[1] is the (unused) mask
  const float* wgt = (const float*)d_in[2];
  float* out       = (float*)d_out;
  sgn_fft_kernel<<<Hh * Ll * 2, 128>>>(x, wgt, out);
}